// round 1
// baseline (speedup 1.0000x reference)
#include <cuda_runtime.h>
#include <math.h>

// ChargeEquilibrationBlock: B=1024 molecules x n=128 atoms.
// Per molecule: build SPD Coulomb matrix A (128x128) + 2 RHS columns in smem,
// Gaussian elimination (no pivoting, SPD-stable), back-substitution, bordered
// correction for the charge-conservation row.
//
// Inputs (metadata order):
//  0: eneg           [N,1]  f32
//  1: positions      [N,3]  f32
//  2: node_attrs     [N,10] f32
//  3: hardness       [10]   f32
//  4: total_charge   [B]    f32
//  5: batch          [N]    i32 (unused: layout is regular, sorted)
//  6: atomic_numbers [N]    i32
// out: partial charges [N] f32

#define NMOL 1024
#define NA   128
#define LD   133      // 133 mod 32 = 5, coprime -> conflict-free column walks
#define NE   10

__global__ __launch_bounds__(NA, 3)
void ceq_kernel(const float* __restrict__ eneg,
                const float* __restrict__ pos,
                const float* __restrict__ attrs,
                const float* __restrict__ hard,
                const float* __restrict__ Qtot,
                const int*   __restrict__ Zs,
                float* __restrict__ out)
{
    extern __shared__ float s[];
    float* A   = s;               // NA x LD  (cols 0..127 = matrix, 128 = -chi, 129 = ones)
    float* sig = s + NA * LD;     // NA : r^2
    float* px  = sig + NA;
    float* py  = px + NA;
    float* pz  = py + NA;
    __shared__ float r1s[4], r2s[4];

    const int mol = blockIdx.x;
    const int tid = threadIdx.x;
    const int gid = mol * NA + tid;

    // ---- per-atom setup ----
    const float x = pos[gid * 3 + 0];
    const float y = pos[gid * 3 + 1];
    const float z = pos[gid * 3 + 2];
    px[tid] = x; py[tid] = y; pz[tid] = z;

    const int Z = Zs[gid];
    const float r = 0.3f + 0.02f * (float)Z;     // COV_RADII[Z]
    const float sg = r * r;
    sig[tid] = sg;

    // argmax over 10 node attrs (first-max semantics)
    const float* arow = attrs + gid * NE;
    int am = 0; float mv = arow[0];
    #pragma unroll
    for (int e = 1; e < NE; e++) { float v = arow[e]; if (v > mv) { mv = v; am = e; } }

    const float diag = hard[am] + 1.0f / (1.7724538509055159f * r);  // sqrt(pi)
    const float negchi = -eneg[gid];
    __syncthreads();

    // ---- build row tid of A ----
    const float inv_sqrt2 = 0.70710678118654752f;
    #pragma unroll 4
    for (int j = 0; j < NA; j++) {
        float v;
        if (j == tid) {
            v = diag;
        } else {
            float dx = x - px[j], dy = y - py[j], dz = z - pz[j];
            float d  = sqrtf(dx * dx + dy * dy + dz * dz);
            float g  = sqrtf(sg + sig[j]);
            v = erff(d * inv_sqrt2 / g) / d;
        }
        A[tid * LD + j] = v;
    }
    A[tid * LD + 128] = negchi;   // RHS 1: -eneg
    A[tid * LD + 129] = 1.0f;     // RHS 2: ones (for bordered correction)

    // ---- forward elimination (no pivoting; A is SPD) ----
    for (int k = 0; k < NA; k++) {
        __syncthreads();
        const float pivinv = 1.0f / A[k * LD + k];
        if (tid > k) {
            const float f = A[tid * LD + k] * pivinv;
            #pragma unroll 4
            for (int j = k + 1; j < NA + 2; j++) {
                A[tid * LD + j] -= f * A[k * LD + j];
            }
        }
    }

    // ---- back substitution, 2 RHS simultaneously ----
    for (int k = NA - 1; k >= 0; k--) {
        __syncthreads();
        const float pivinv = 1.0f / A[k * LD + k];
        const float x1 = A[k * LD + 128] * pivinv;
        const float x2 = A[k * LD + 129] * pivinv;
        __syncthreads();   // all reads of row k done before thread k overwrites
        if (tid < k) {
            const float aik = A[tid * LD + k];
            A[tid * LD + 128] -= aik * x1;
            A[tid * LD + 129] -= aik * x2;
        } else if (tid == k) {
            A[k * LD + 128] = x1;
            A[k * LD + 129] = x2;
        }
    }
    __syncthreads();

    const float yv = A[tid * LD + 128];   // y = A^{-1}(-chi)
    const float zv = A[tid * LD + 129];   // z = A^{-1} 1

    // ---- reductions: s1 = 1^T y, s2 = 1^T z ----
    float s1 = yv, s2 = zv;
    #pragma unroll
    for (int o = 16; o > 0; o >>= 1) {
        s1 += __shfl_xor_sync(0xffffffffu, s1, o);
        s2 += __shfl_xor_sync(0xffffffffu, s2, o);
    }
    const int w = tid >> 5;
    if ((tid & 31) == 0) { r1s[w] = s1; r2s[w] = s2; }
    __syncthreads();
    s1 = r1s[0] + r1s[1] + r1s[2] + r1s[3];
    s2 = r2s[0] + r2s[1] + r2s[2] + r2s[3];

    // bordered system: lambda = (1^T y - Q) / (1^T z - 1);  q = y - lambda z
    const float lam = (s1 - Qtot[mol]) / (s2 - 1.0f);
    out[gid] = yv - lam * zv;
}

extern "C" void kernel_launch(void* const* d_in, const int* in_sizes, int n_in,
                              void* d_out, int out_size)
{
    const float* eneg  = (const float*)d_in[0];
    const float* pos   = (const float*)d_in[1];
    const float* attrs = (const float*)d_in[2];
    const float* hard  = (const float*)d_in[3];
    const float* Qtot  = (const float*)d_in[4];
    // d_in[5] = batch (unused; regular layout)
    const int*   Zs    = (const int*)d_in[6];
    float* out = (float*)d_out;

    const int smem = (NA * LD + 4 * NA) * (int)sizeof(float);  // 70144 B
    cudaFuncSetAttribute(ceq_kernel, cudaFuncAttributeMaxDynamicSharedMemorySize, smem);

    ceq_kernel<<<NMOL, NA, smem>>>(eneg, pos, attrs, hard, Qtot, Zs, out);
}

// round 2
// speedup vs baseline: 1.3734x; 1.3734x over previous
#include <cuda_runtime.h>
#include <math.h>

// ChargeEquilibrationBlock: B=1024 molecules x n=128 atoms.
// Per molecule: build lower triangle of the SPD Coulomb matrix in smem,
// Cholesky factorize (1 barrier/step, double-buffered column publish,
// float4 trailing updates), two triangular solves with RHS in registers,
// bordered correction for the charge-conservation row.
//
// Inputs (metadata order):
//  0: eneg [N,1] f32   1: positions [N,3] f32   2: node_attrs [N,10] f32
//  3: hardness [10] f32  4: total_charge [B] f32  5: batch [N] i32 (unused)
//  6: atomic_numbers [N] i32      out: charges [N] f32

#define NMOL 1024
#define NA   128
#define LD   132      // stride 132 = 4 mod 32: float4 row walks conflict-free
#define NE   10

__global__ __launch_bounds__(NA, 3)
void ceq_kernel(const float* __restrict__ eneg,
                const float* __restrict__ pos,
                const float* __restrict__ attrs,
                const float* __restrict__ hard,
                const float* __restrict__ Qtot,
                const int*   __restrict__ Zs,
                float* __restrict__ out)
{
    extern __shared__ float s[];
    float* A    = s;               // NA x LD, lower triangle used (row i: cols 0..i)
    float* ck0  = A + NA * LD;     // published pivot column, parity 0
    float* ck1  = ck0 + NA;        // parity 1
    float* xb1  = ck1 + NA;        // publish buffer RHS 1
    float* xb2  = xb1 + NA;        // publish buffer RHS 2
    float* px   = xb2 + NA;
    float* py   = px  + NA;
    float* pz   = py  + NA;
    float* sig  = pz  + NA;
    __shared__ float r1s[4], r2s[4];

    const int mol = blockIdx.x;
    const int tid = threadIdx.x;
    const int gid = mol * NA + tid;

    // ---- per-atom setup ----
    const float x = pos[gid * 3 + 0];
    const float y = pos[gid * 3 + 1];
    const float z = pos[gid * 3 + 2];
    px[tid] = x; py[tid] = y; pz[tid] = z;

    const int Z = Zs[gid];
    const float r  = 0.3f + 0.02f * (float)Z;      // COV_RADII[Z]
    const float sg = r * r;
    sig[tid] = sg;

    const float* arow = attrs + gid * NE;          // first-max argmax
    int am = 0; float mv = arow[0];
    #pragma unroll
    for (int e = 1; e < NE; e++) { float v = arow[e]; if (v > mv) { mv = v; am = e; } }

    const float diag = hard[am] + 1.0f / (1.7724538509055159f * r);   // sqrt(pi)
    float b1 = -eneg[gid];                          // RHS 1: -chi
    float b2 = 1.0f;                                // RHS 2: ones
    __syncthreads();

    // ---- build lower-triangle row tid ----
    const float inv_sqrt2 = 0.70710678118654752f;
    for (int j = 0; j < tid; j++) {
        float dx = x - px[j], dy = y - py[j], dz = z - pz[j];
        float d  = sqrtf(dx * dx + dy * dy + dz * dz);
        float gi = rsqrtf(sg + sig[j]);             // 1/gamma
        A[tid * LD + j] = erff(d * inv_sqrt2 * gi) / d;
    }
    A[tid * LD + tid] = diag;
    __syncthreads();

    // ---- Cholesky: one barrier per step ----
    for (int k = 0; k < NA; k++) {
        float* ck = (k & 1) ? ck1 : ck0;           // double buffer kills WAR hazard
        float cown = 0.0f;
        if (tid >= k) {                            // own row value, updated by self last step
            cown = A[tid * LD + k];
            ck[tid] = cown;
        }
        __syncthreads();                           // publish visible
        const float akk  = ck[k];
        const float rinv = rsqrtf(akk);
        if (tid >= k) {
            A[tid * LD + k] = cown * rinv;         // store L[tid,k]
            const float g = cown * (rinv * rinv);  // cown / akk
            int j  = k + 1;
            const int je = tid;                    // inclusive end (lower triangle)
            const int jal = (j + 3) & ~3;
            for (; j <= je && j < jal; j++)        // scalar head to 16B alignment
                A[tid * LD + j] -= g * ck[j];
            for (; j + 3 <= je; j += 4) {          // float4 body (conflict-free)
                float4 cv = *(const float4*)&ck[j];
                float4 av = *(float4*)&A[tid * LD + j];
                av.x -= g * cv.x; av.y -= g * cv.y;
                av.z -= g * cv.z; av.w -= g * cv.w;
                *(float4*)&A[tid * LD + j] = av;
            }
            for (; j <= je; j++)                   // scalar tail
                A[tid * LD + j] -= g * ck[j];
        }
    }

    // ---- forward solve L y = b (both RHS, RHS in registers) ----
    for (int k = 0; k < NA; k++) {
        if (tid == k) {
            const float inv = 1.0f / A[k * LD + k];
            xb1[k] = b1 * inv;
            xb2[k] = b2 * inv;
        }
        __syncthreads();
        if (tid > k) {
            const float l = A[tid * LD + k];
            b1 -= l * xb1[k];
            b2 -= l * xb2[k];
        }
    }
    float y1 = xb1[tid], y2 = xb2[tid];
    __syncthreads();                               // all y reads done before reuse of xb*

    // ---- backward solve L^T x = y ----
    for (int k = NA - 1; k >= 0; k--) {
        if (tid == k) {
            const float inv = 1.0f / A[k * LD + k];
            xb1[k] = y1 * inv;
            xb2[k] = y2 * inv;
        }
        __syncthreads();
        if (tid < k) {
            const float l = A[k * LD + tid];       // row k, contiguous: conflict-free
            y1 -= l * xb1[k];
            y2 -= l * xb2[k];
        }
    }
    const float yv = xb1[tid];                     // y = A^{-1}(-chi)
    const float zv = xb2[tid];                     // z = A^{-1} 1

    // ---- reductions: s1 = 1^T y, s2 = 1^T z ----
    float s1 = yv, s2 = zv;
    #pragma unroll
    for (int o = 16; o > 0; o >>= 1) {
        s1 += __shfl_xor_sync(0xffffffffu, s1, o);
        s2 += __shfl_xor_sync(0xffffffffu, s2, o);
    }
    const int w = tid >> 5;
    if ((tid & 31) == 0) { r1s[w] = s1; r2s[w] = s2; }
    __syncthreads();
    s1 = r1s[0] + r1s[1] + r1s[2] + r1s[3];
    s2 = r2s[0] + r2s[1] + r2s[2] + r2s[3];

    // bordered system: lambda = (1^T y - Q)/(1^T z - 1);  q = y - lambda z
    const float lam = (s1 - Qtot[mol]) / (s2 - 1.0f);
    out[gid] = yv - lam * zv;
}

extern "C" void kernel_launch(void* const* d_in, const int* in_sizes, int n_in,
                              void* d_out, int out_size)
{
    const float* eneg  = (const float*)d_in[0];
    const float* pos   = (const float*)d_in[1];
    const float* attrs = (const float*)d_in[2];
    const float* hard  = (const float*)d_in[3];
    const float* Qtot  = (const float*)d_in[4];
    const int*   Zs    = (const int*)d_in[6];
    float* out = (float*)d_out;

    const int smem = (NA * LD + 8 * NA) * (int)sizeof(float);   // 71680 B
    cudaFuncSetAttribute(ceq_kernel, cudaFuncAttributeMaxDynamicSharedMemorySize, smem);

    ceq_kernel<<<NMOL, NA, smem>>>(eneg, pos, attrs, hard, Qtot, Zs, out);
}

// round 3
// speedup vs baseline: 2.4402x; 1.7768x over previous
#include <cuda_runtime.h>
#include <math.h>

// ChargeEquilibrationBlock: B=1024 molecules x n=128 atoms.
// Blocked (NB=32) right-looking Cholesky in shared memory:
//   - panel factorization: warp-internal (shuffle exchange, no CTA barriers)
//   - TRSM: per-thread register triangular solve vs broadcast panel
//   - trailing: rank-32 register-blocked update (float4 broadcast loads)
//   - solves: blocked, warp-shuffle diagonal solves + rect updates
// Bordered charge-conservation system handled by 2-RHS + Schur correction.

#define NMOL 1024
#define NA   128
#define LD   132      // 132 mod 32 = 4: float4 row walks conflict-free
#define NB   32
#define NBLK (NA/NB)
#define NE   10
#define FULL 0xffffffffu

__global__ __launch_bounds__(NA, 3)
void ceq_kernel(const float* __restrict__ eneg,
                const float* __restrict__ pos,
                const float* __restrict__ attrs,
                const float* __restrict__ hard,
                const float* __restrict__ Qtot,
                const int*   __restrict__ Zs,
                float* __restrict__ out)
{
    extern __shared__ float s[];
    float* A     = s;               // NA x LD, lower triangle (row i: cols 0..i)
    float* rinvS = A + NA * LD;     // 128: 1/L_ii
    float* xs1   = rinvS + NA;      // solve broadcast, RHS 1
    float* xs2   = xs1 + NA;        // solve broadcast, RHS 2
    float* px    = xs2 + NA;
    float* py    = px + NA;
    float* pz    = py + NA;
    float* sig   = pz + NA;
    __shared__ float r1s[4], r2s[4];

    const int mol  = blockIdx.x;
    const int tid  = threadIdx.x;
    const int lane = tid & 31;
    const int wid  = tid >> 5;
    const int gid  = mol * NA + tid;
    float* Arow = A + tid * LD;

    // ---- per-atom setup ----
    const float x = pos[gid * 3 + 0];
    const float y = pos[gid * 3 + 1];
    const float z = pos[gid * 3 + 2];
    px[tid] = x; py[tid] = y; pz[tid] = z;

    const int Z = Zs[gid];
    const float r  = 0.3f + 0.02f * (float)Z;       // COV_RADII[Z]
    const float sg = r * r;
    sig[tid] = sg;

    const float* arow = attrs + gid * NE;           // first-max argmax
    int am = 0; float mv = arow[0];
    #pragma unroll
    for (int e = 1; e < NE; e++) { float v = arow[e]; if (v > mv) { mv = v; am = e; } }

    const float diag = hard[am] + 1.0f / (1.7724538509055159f * r);  // sqrt(pi)
    float v1 = -eneg[gid];                          // RHS 1: -chi
    float v2 = 1.0f;                                // RHS 2: ones
    __syncthreads();

    // ---- build lower-triangle row tid ----
    const float is2 = 0.70710678118654752f;
    for (int j = 0; j < tid; j++) {
        float dx = x - px[j], dy = y - py[j], dz = z - pz[j];
        float d  = sqrtf(dx * dx + dy * dy + dz * dz);
        float gi = rsqrtf(sg + sig[j]);
        Arow[j] = erff(d * is2 * gi) / d;
    }
    Arow[tid] = diag;
    __syncthreads();

    // ---- blocked Cholesky ----
    for (int b = 0; b < NBLK; b++) {
        const int kb = b * NB;

        // (1) panel factorization: warp b, rows kb..kb+31, cols kb..kb+31
        if (wid == b) {
            for (int m = 0; m < NB; m++) {
                __syncwarp();                        // prior column writes visible
                const int cm = kb + m;
                const float dg = A[cm * LD + cm];    // broadcast of updated diag
                const float rv = rsqrtf(dg);
                float lv = 0.0f;
                if (lane == m) { Arow[cm] = dg * rv; rinvS[cm] = rv; }
                else if (lane > m) { lv = Arow[cm] * rv; Arow[cm] = lv; }
                for (int j = m + 1; j < NB; j++) {   // uniform trip count: shfl legal
                    float ljm = __shfl_sync(FULL, lv, j);
                    if (j <= lane) Arow[kb + j] -= lv * ljm;
                }
            }
        }
        __syncthreads();                             // panel + rinvS visible

        // (2) TRSM: rows below panel compute their 32 L-values into registers
        const bool below = (tid >= kb + NB);
        float Lreg[NB];
        if (below) {
            #pragma unroll
            for (int m = 0; m < NB; m++) {
                const float* Pm = A + (kb + m) * LD + kb;   // panel row m (broadcast)
                float ve = 0.0f, vo = 0.0f;
                #pragma unroll
                for (int t = 0; t < m; t++) {
                    if (t & 1) vo += Lreg[t] * Pm[t];
                    else       ve += Lreg[t] * Pm[t];
                }
                Lreg[m] = (Arow[kb + m] - ve - vo) * rinvS[kb + m];
            }
            #pragma unroll
            for (int m = 0; m < NB; m += 4)
                *(float4*)&Arow[kb + m] =
                    make_float4(Lreg[m], Lreg[m+1], Lreg[m+2], Lreg[m+3]);
        }
        __syncthreads();                             // L columns visible

        // (3) trailing update: A[i][j] -= sum_t Lreg[t] * L[j][t], lockstep j
        if (below) {
            for (int j = kb + NB; j <= tid; j++) {
                const float* Lj = A + j * LD + kb;   // same row across threads: broadcast
                float lj[NB];
                #pragma unroll
                for (int q = 0; q < NB; q += 4) {
                    float4 t4 = *(const float4*)(Lj + q);
                    lj[q] = t4.x; lj[q+1] = t4.y; lj[q+2] = t4.z; lj[q+3] = t4.w;
                }
                float a0 = 0.f, a1 = 0.f, a2 = 0.f, a3 = 0.f;
                #pragma unroll
                for (int t = 0; t < NB; t += 4) {
                    a0 += Lreg[t    ] * lj[t    ];
                    a1 += Lreg[t + 1] * lj[t + 1];
                    a2 += Lreg[t + 2] * lj[t + 2];
                    a3 += Lreg[t + 3] * lj[t + 3];
                }
                Arow[j] -= (a0 + a1) + (a2 + a3);
            }
        }
        // no barrier: next panel touches only warp b+1's own rows/cols (disjoint),
        // and the panel's __syncwarp provides intra-warp visibility.
    }

    // ---- forward solve L y = b (2 RHS), blocked ----
    for (int b = 0; b < NBLK; b++) {
        const int kb = b * NB;
        if (wid == b) {
            float lrow[NB];                          // own L row segment
            #pragma unroll
            for (int q = 0; q < NB; q += 4) {
                float4 t4 = *(const float4*)&Arow[kb + q];
                lrow[q] = t4.x; lrow[q+1] = t4.y; lrow[q+2] = t4.z; lrow[q+3] = t4.w;
            }
            const float rv = rinvS[tid];
            #pragma unroll
            for (int m = 0; m < NB; m++) {
                float x1 = __shfl_sync(FULL, v1 * rv, m);
                float x2 = __shfl_sync(FULL, v2 * rv, m);
                if (lane > m) { v1 -= lrow[m] * x1; v2 -= lrow[m] * x2; }
            }
            v1 *= rv; v2 *= rv;                      // y for this row
            xs1[tid] = v1; xs2[tid] = v2;
        }
        __syncthreads();
        if (tid >= kb + NB) {
            float lrow[NB];
            #pragma unroll
            for (int q = 0; q < NB; q += 4) {
                float4 t4 = *(const float4*)&Arow[kb + q];
                lrow[q] = t4.x; lrow[q+1] = t4.y; lrow[q+2] = t4.z; lrow[q+3] = t4.w;
            }
            #pragma unroll
            for (int m = 0; m < NB; m++) {
                v1 -= lrow[m] * xs1[kb + m];
                v2 -= lrow[m] * xs2[kb + m];
            }
        }
    }

    // ---- backward solve L^T x = y (2 RHS), blocked ----
    for (int b = NBLK - 1; b >= 0; b--) {
        const int kb = b * NB;
        if (wid == b) {
            float lcol[NB];                          // column tid of panel rows
            #pragma unroll
            for (int m = 0; m < NB; m++)
                lcol[m] = A[(kb + m) * LD + tid];    // consecutive tid: conflict-free
            const float rv = rinvS[tid];
            #pragma unroll
            for (int m = NB - 1; m >= 0; m--) {
                float x1 = __shfl_sync(FULL, v1 * rv, m);
                float x2 = __shfl_sync(FULL, v2 * rv, m);
                if (lane < m) { v1 -= lcol[m] * x1; v2 -= lcol[m] * x2; }
            }
            v1 *= rv; v2 *= rv;                      // x for this row
            xs1[tid] = v1; xs2[tid] = v2;
        }
        __syncthreads();
        if (tid < kb) {
            #pragma unroll
            for (int m = 0; m < NB; m++) {
                float l = A[(kb + m) * LD + tid];    // conflict-free column read
                v1 -= l * xs1[kb + m];
                v2 -= l * xs2[kb + m];
            }
        }
    }

    // v1 = y-solution (A^{-1}(-chi)), v2 = z-solution (A^{-1} 1)
    float s1 = v1, s2 = v2;
    #pragma unroll
    for (int o = 16; o > 0; o >>= 1) {
        s1 += __shfl_xor_sync(FULL, s1, o);
        s2 += __shfl_xor_sync(FULL, s2, o);
    }
    if (lane == 0) { r1s[wid] = s1; r2s[wid] = s2; }
    __syncthreads();
    s1 = r1s[0] + r1s[1] + r1s[2] + r1s[3];
    s2 = r2s[0] + r2s[1] + r2s[2] + r2s[3];

    const float lam = (s1 - Qtot[mol]) / (s2 - 1.0f);
    out[gid] = v1 - lam * v2;
}

extern "C" void kernel_launch(void* const* d_in, const int* in_sizes, int n_in,
                              void* d_out, int out_size)
{
    const float* eneg  = (const float*)d_in[0];
    const float* pos   = (const float*)d_in[1];
    const float* attrs = (const float*)d_in[2];
    const float* hard  = (const float*)d_in[3];
    const float* Qtot  = (const float*)d_in[4];
    const int*   Zs    = (const int*)d_in[6];
    float* out = (float*)d_out;

    const int smem = (NA * LD + 8 * NA) * (int)sizeof(float);   // 71168 B
    cudaFuncSetAttribute(ceq_kernel, cudaFuncAttributeMaxDynamicSharedMemorySize, smem);

    ceq_kernel<<<NMOL, NA, smem>>>(eneg, pos, attrs, hard, Qtot, Zs, out);
}

// round 4
// speedup vs baseline: 2.8167x; 1.1543x over previous
#include <cuda_runtime.h>
#include <math.h>

// ChargeEquilibrationBlock: B=1024 molecules x n=128 atoms.
// Blocked (NB=32) Cholesky on a PACKED lower triangle (16B-aligned rows,
// 33.8KB vs 67.6KB square) -> 5 CTAs/SM instead of 3: more latency hiding,
// 2 waves instead of 3. Panel = warp-internal shuffle; TRSM = register
// triangular solve; trailing = rank-32 register-blocked FFMA stream.
// Bordered charge-conservation handled via 2 RHS + Schur correction.

#define NMOL 1024
#define NA   128
#define NB   32
#define NBLK (NA/NB)
#define NE   10
#define FULL 0xffffffffu
#define TRI_WORDS 8448   // rowp(128)

// packed row offset: rows padded to multiple of 4 words (16B aligned)
__device__ __forceinline__ int rowp(int i) {
    const int q = i >> 2, r = i & 3;
    return ((q * (q - 1)) << 3) + ((r * q) << 2) + (i << 2);
}
// rowp(j+1) - rowp(j) = (j & ~3) + 4

__global__ __launch_bounds__(NA, 5)
void ceq_kernel(const float* __restrict__ eneg,
                const float* __restrict__ pos,
                const float* __restrict__ attrs,
                const float* __restrict__ hard,
                const float* __restrict__ Qtot,
                const int*   __restrict__ Zs,
                float* __restrict__ out)
{
    extern __shared__ float s[];
    float* A     = s;                  // packed lower triangle, TRI_WORDS
    float* rinvS = A + TRI_WORDS;      // 128: 1/L_ii
    float* xs1   = rinvS + NA;         // solve broadcast, RHS 1
    float* xs2   = xs1 + NA;
    float* px    = xs2 + NA;
    float* py    = px + NA;
    float* pz    = py + NA;
    float* sig   = pz + NA;
    __shared__ float r1s[4], r2s[4];

    const int mol  = blockIdx.x;
    const int tid  = threadIdx.x;
    const int lane = tid & 31;
    const int wid  = tid >> 5;
    const int gid  = mol * NA + tid;
    float* Arow = A + rowp(tid);       // row tid: cols 0..tid

    // ---- per-atom setup ----
    const float x = pos[gid * 3 + 0];
    const float y = pos[gid * 3 + 1];
    const float z = pos[gid * 3 + 2];
    px[tid] = x; py[tid] = y; pz[tid] = z;

    const int Z = Zs[gid];
    const float r  = 0.3f + 0.02f * (float)Z;       // COV_RADII[Z]
    const float sg = r * r;
    sig[tid] = sg;

    const float* arow = attrs + gid * NE;           // first-max argmax
    int am = 0; float mv = arow[0];
    #pragma unroll
    for (int e = 1; e < NE; e++) { float v = arow[e]; if (v > mv) { mv = v; am = e; } }

    const float diag = hard[am] + 1.0f / (1.7724538509055159f * r);  // sqrt(pi)
    float v1 = -eneg[gid];                          // RHS 1: -chi
    float v2 = 1.0f;                                // RHS 2: ones
    __syncthreads();

    // ---- build packed lower-triangle row tid ----
    const float is2 = 0.70710678118654752f;
    for (int j = 0; j < tid; j++) {
        float dx = x - px[j], dy = y - py[j], dz = z - pz[j];
        float d  = sqrtf(dx * dx + dy * dy + dz * dz);
        float gi = rsqrtf(sg + sig[j]);
        Arow[j] = erff(d * is2 * gi) / d;
    }
    Arow[tid] = diag;
    __syncthreads();

    // ---- blocked Cholesky ----
    for (int b = 0; b < NBLK; b++) {
        const int kb = b * NB;

        // (1) panel factorization: warp b, rows/cols kb..kb+31
        if (wid == b) {
            int doff = rowp(kb);                    // offset of row kb
            for (int m = 0; m < NB; m++) {
                __syncwarp();
                const int cm = kb + m;
                const float dg = A[doff + cm];      // updated diag (broadcast)
                const float rv = rsqrtf(dg);
                float lv = 0.0f;
                if (lane == m) { Arow[cm] = dg * rv; rinvS[cm] = rv; }
                else if (lane > m) { lv = Arow[cm] * rv; Arow[cm] = lv; }
                for (int j = m + 1; j < NB; j++) {  // uniform trip: shfl legal
                    float ljm = __shfl_sync(FULL, lv, j);
                    if (j <= lane) Arow[kb + j] -= lv * ljm;
                }
                doff += (cm & ~3) + 4;              // advance to row cm+1
            }
        }
        __syncthreads();                            // panel + rinvS visible

        // (2) TRSM: rows below panel -> 32 L-values in registers
        const bool below = (tid >= kb + NB);
        float Lreg[NB];
        if (below) {
            int poff = rowp(kb);
            #pragma unroll
            for (int m = 0; m < NB; m++) {
                const float* Pm = A + poff + kb;    // panel row m (broadcast)
                float ve = 0.0f, vo = 0.0f;
                #pragma unroll
                for (int t = 0; t < m; t++) {
                    if (t & 1) vo += Lreg[t] * Pm[t];
                    else       ve += Lreg[t] * Pm[t];
                }
                Lreg[m] = (Arow[kb + m] - ve - vo) * rinvS[kb + m];
                poff += kb + (m & ~3) + 4;          // rowp(kb+m+1)-rowp(kb+m)
            }
            #pragma unroll
            for (int m = 0; m < NB; m += 4)
                *(float4*)&Arow[kb + m] =
                    make_float4(Lreg[m], Lreg[m+1], Lreg[m+2], Lreg[m+3]);
        }
        __syncthreads();                            // L columns visible

        // (3) trailing: A[tid][j] -= sum_t Lreg[t]*L[j][t], lockstep j
        if (below) {
            int joff = rowp(kb + NB);
            for (int j = kb + NB; j <= tid; j++) {
                const float4* Lj = (const float4*)(A + joff + kb);  // broadcast
                float a0 = 0.f, a1 = 0.f, a2 = 0.f, a3 = 0.f;
                #pragma unroll
                for (int q = 0; q < NB / 4; q++) {
                    float4 c = Lj[q];
                    a0 += Lreg[4*q    ] * c.x;
                    a1 += Lreg[4*q + 1] * c.y;
                    a2 += Lreg[4*q + 2] * c.z;
                    a3 += Lreg[4*q + 3] * c.w;
                }
                Arow[j] -= (a0 + a1) + (a2 + a3);
                joff += (j & ~3) + 4;
            }
        }
        // no CTA barrier: panel b+1's warp only touches rows it itself updated
    }

    // ---- forward solve L y = b (2 RHS), blocked ----
    for (int b = 0; b < NBLK; b++) {
        const int kb = b * NB;
        if (wid == b) {
            float lrow[NB];
            #pragma unroll
            for (int q = 0; q < NB; q += 4) {
                float4 t4 = *(const float4*)&Arow[kb + q];
                lrow[q] = t4.x; lrow[q+1] = t4.y; lrow[q+2] = t4.z; lrow[q+3] = t4.w;
            }
            const float rv = rinvS[tid];
            #pragma unroll
            for (int m = 0; m < NB; m++) {
                float x1 = __shfl_sync(FULL, v1 * rv, m);
                float x2 = __shfl_sync(FULL, v2 * rv, m);
                if (lane > m) { v1 -= lrow[m] * x1; v2 -= lrow[m] * x2; }
            }
            v1 *= rv; v2 *= rv;
            xs1[tid] = v1; xs2[tid] = v2;
        }
        __syncthreads();
        if (tid >= kb + NB) {
            #pragma unroll
            for (int q = 0; q < NB; q += 4) {
                float4 t4 = *(const float4*)&Arow[kb + q];
                v1 -= t4.x * xs1[kb+q]   + t4.y * xs1[kb+q+1]
                    + t4.z * xs1[kb+q+2] + t4.w * xs1[kb+q+3];
                v2 -= t4.x * xs2[kb+q]   + t4.y * xs2[kb+q+1]
                    + t4.z * xs2[kb+q+2] + t4.w * xs2[kb+q+3];
            }
        }
    }

    // ---- backward solve L^T x = y (2 RHS), blocked ----
    for (int b = NBLK - 1; b >= 0; b--) {
        const int kb = b * NB;
        if (wid == b) {
            float lcol[NB];
            int coff = rowp(kb);
            #pragma unroll
            for (int m = 0; m < NB; m++) {
                lcol[m] = A[coff + tid];            // consecutive lanes: no conflict
                coff += kb + (m & ~3) + 4;
            }
            const float rv = rinvS[tid];
            #pragma unroll
            for (int m = NB - 1; m >= 0; m--) {
                float x1 = __shfl_sync(FULL, v1 * rv, m);
                float x2 = __shfl_sync(FULL, v2 * rv, m);
                if (lane < m) { v1 -= lcol[m] * x1; v2 -= lcol[m] * x2; }
            }
            v1 *= rv; v2 *= rv;
            xs1[tid] = v1; xs2[tid] = v2;
        }
        __syncthreads();
        if (tid < kb) {
            int coff = rowp(kb);
            #pragma unroll
            for (int m = 0; m < NB; m++) {
                float l = A[coff + tid];
                v1 -= l * xs1[kb + m];
                v2 -= l * xs2[kb + m];
                coff += kb + (m & ~3) + 4;
            }
        }
    }

    // v1 = A^{-1}(-chi), v2 = A^{-1} 1
    float s1 = v1, s2 = v2;
    #pragma unroll
    for (int o = 16; o > 0; o >>= 1) {
        s1 += __shfl_xor_sync(FULL, s1, o);
        s2 += __shfl_xor_sync(FULL, s2, o);
    }
    if (lane == 0) { r1s[wid] = s1; r2s[wid] = s2; }
    __syncthreads();
    s1 = r1s[0] + r1s[1] + r1s[2] + r1s[3];
    s2 = r2s[0] + r2s[1] + r2s[2] + r2s[3];

    const float lam = (s1 - Qtot[mol]) / (s2 - 1.0f);
    out[gid] = v1 - lam * v2;
}

extern "C" void kernel_launch(void* const* d_in, const int* in_sizes, int n_in,
                              void* d_out, int out_size)
{
    const float* eneg  = (const float*)d_in[0];
    const float* pos   = (const float*)d_in[1];
    const float* attrs = (const float*)d_in[2];
    const float* hard  = (const float*)d_in[3];
    const float* Qtot  = (const float*)d_in[4];
    const int*   Zs    = (const int*)d_in[6];
    float* out = (float*)d_out;

    const int smem = (TRI_WORDS + 7 * NA) * (int)sizeof(float);   // 37376 B
    cudaFuncSetAttribute(ceq_kernel, cudaFuncAttributeMaxDynamicSharedMemorySize, smem);

    ceq_kernel<<<NMOL, NA, smem>>>(eneg, pos, attrs, hard, Qtot, Zs, out);
}

// round 5
// speedup vs baseline: 2.9524x; 1.0482x over previous
#include <cuda_runtime.h>
#include <math.h>

// ChargeEquilibrationBlock: B=1024 molecules x n=128 atoms.
// Packed-triangle blocked Cholesky (NB=32) with the forward solve FUSED into
// the factorization (panel warp solves its diag block right after factoring;
// below rows fold the RHS update into TRSM using register-resident Lreg).
// Trailing update processes 4 rows per iteration (32 broadcast LDS.128,
// 128 FFMA, one float4 RMW) for high MLP. 6 CTAs/SM.

#define NMOL 1024
#define NA   128
#define NB   32
#define NBLK (NA/NB)
#define NE   10
#define FULL 0xffffffffu
#define TRI_WORDS 8448   // rowp(128)

// packed row offset: rows padded to multiple of 4 words (16B aligned)
__device__ __forceinline__ int rowp(int i) {
    const int q = i >> 2, r = i & 3;
    return ((q * (q - 1)) << 3) + ((r * q) << 2) + (i << 2);
}
// rowp(j+1) - rowp(j) = (j & ~3) + 4

__global__ __launch_bounds__(NA, 6)
void ceq_kernel(const float* __restrict__ eneg,
                const float* __restrict__ pos,
                const float* __restrict__ attrs,
                const float* __restrict__ hard,
                const float* __restrict__ Qtot,
                const int*   __restrict__ Zs,
                float* __restrict__ out)
{
    extern __shared__ float s[];
    float*  A     = s;                    // packed lower triangle
    float*  rinvS = A + TRI_WORDS;        // 128: 1/L_ii
    float*  xs1   = rinvS + NA;           // solve broadcast, RHS 1
    float*  xs2   = xs1 + NA;             // solve broadcast, RHS 2
    float4* pq    = (float4*)(xs2 + NA);  // 128: (x, y, z, sigma)
    __shared__ float r1s[4], r2s[4];

    const int mol  = blockIdx.x;
    const int tid  = threadIdx.x;
    const int lane = tid & 31;
    const int wid  = tid >> 5;
    const int gid  = mol * NA + tid;
    float* Arow = A + rowp(tid);          // row tid: cols 0..tid

    // ---- per-atom setup ----
    const float x = pos[gid * 3 + 0];
    const float y = pos[gid * 3 + 1];
    const float z = pos[gid * 3 + 2];
    const int Z = Zs[gid];
    const float r  = 0.3f + 0.02f * (float)Z;       // COV_RADII[Z]
    const float sg = r * r;
    pq[tid] = make_float4(x, y, z, sg);

    const float* arow = attrs + gid * NE;           // first-max argmax
    int am = 0; float mv = arow[0];
    #pragma unroll
    for (int e = 1; e < NE; e++) { float v = arow[e]; if (v > mv) { mv = v; am = e; } }

    const float diag = hard[am] + 1.0f / (1.7724538509055159f * r);  // sqrt(pi)
    float v1 = -eneg[gid];                          // RHS 1: -chi
    float v2 = 1.0f;                                // RHS 2: ones
    __syncthreads();

    // ---- build packed lower-triangle row tid ----
    const float is2 = 0.70710678118654752f;
    for (int j = 0; j < tid; j++) {
        float4 p = pq[j];                            // broadcast LDS.128
        float dx = x - p.x, dy = y - p.y, dz = z - p.z;
        float d  = sqrtf(dx * dx + dy * dy + dz * dz);
        float gi = rsqrtf(sg + p.w);
        Arow[j] = erff(d * is2 * gi) / d;
    }
    Arow[tid] = diag;
    __syncthreads();

    // ---- blocked Cholesky with fused forward solve ----
    for (int b = 0; b < NBLK; b++) {
        const int kb = b * NB;

        // (1) panel factorization (warp b) + diag forward solve
        if (wid == b) {
            int doff = rowp(kb);
            for (int m = 0; m < NB; m++) {
                __syncwarp();
                const int cm = kb + m;
                const float dg = A[doff + cm];       // updated diag (broadcast)
                const float rv = rsqrtf(dg);
                float lv = 0.0f;
                if (lane == m) { Arow[cm] = dg * rv; rinvS[cm] = rv; }
                else if (lane > m) { lv = Arow[cm] * rv; Arow[cm] = lv; }
                for (int j = m + 1; j < NB; j++) {   // uniform trip: shfl legal
                    float ljm = __shfl_sync(FULL, lv, j);
                    if (j <= lane) Arow[kb + j] -= lv * ljm;
                }
                doff += (cm & ~3) + 4;
            }
            __syncwarp();
            // forward diag solve: L_bb y = b_panel (RHS already updated by
            // all previous blocks through the fused TRSM-phase updates)
            float lrow[NB];
            #pragma unroll
            for (int q = 0; q < NB; q += 4) {
                float4 t4 = *(const float4*)&Arow[kb + q];
                lrow[q] = t4.x; lrow[q+1] = t4.y; lrow[q+2] = t4.z; lrow[q+3] = t4.w;
            }
            const float rv = rinvS[tid];
            #pragma unroll
            for (int m = 0; m < NB; m++) {
                float x1 = __shfl_sync(FULL, v1 * rv, m);
                float x2 = __shfl_sync(FULL, v2 * rv, m);
                if (lane > m) { v1 -= lrow[m] * x1; v2 -= lrow[m] * x2; }
            }
            v1 *= rv; v2 *= rv;                      // y for this row
            xs1[tid] = v1; xs2[tid] = v2;
        }
        __syncthreads();                             // panel + rinvS + y visible

        // (2) TRSM below panel (Lreg in registers) + fused RHS update
        const bool below = (tid >= kb + NB);
        float Lreg[NB];
        if (below) {
            int poff = rowp(kb);
            #pragma unroll
            for (int m = 0; m < NB; m++) {
                const float* Pm = A + poff + kb;     // panel row m (broadcast)
                float ve = 0.0f, vo = 0.0f;
                #pragma unroll
                for (int t = 0; t < m; t++) {
                    if (t & 1) vo += Lreg[t] * Pm[t];
                    else       ve += Lreg[t] * Pm[t];
                }
                Lreg[m] = (Arow[kb + m] - ve - vo) * rinvS[kb + m];
                poff += kb + (m & ~3) + 4;
            }
            #pragma unroll
            for (int m = 0; m < NB; m += 4)
                *(float4*)&Arow[kb + m] =
                    make_float4(Lreg[m], Lreg[m+1], Lreg[m+2], Lreg[m+3]);
            // forward RHS update: v -= L_row(panel) . y_panel  (Lreg in regs)
            #pragma unroll
            for (int q = 0; q < NB; q += 4) {
                float4 a1 = *(const float4*)&xs1[kb + q];
                float4 a2 = *(const float4*)&xs2[kb + q];
                v1 -= Lreg[q]*a1.x + Lreg[q+1]*a1.y + Lreg[q+2]*a1.z + Lreg[q+3]*a1.w;
                v2 -= Lreg[q]*a2.x + Lreg[q+1]*a2.y + Lreg[q+2]*a2.z + Lreg[q+3]*a2.w;
            }
        }
        __syncthreads();                             // L columns visible

        // (3) trailing update, 4 rows per iteration
        if (below) {
            int j    = kb + NB;                      // multiple of 4
            int joff = rowp(j);
            for (; j + 3 <= tid; j += 4) {
                const int len = j + 4;               // padded row length (j mult 4)
                const float4* R0 = (const float4*)(A + joff             + kb);
                const float4* R1 = (const float4*)(A + joff +     len   + kb);
                const float4* R2 = (const float4*)(A + joff + 2 * len   + kb);
                const float4* R3 = (const float4*)(A + joff + 3 * len   + kb);
                float a0 = 0.f, a1 = 0.f, a2 = 0.f, a3 = 0.f;
                #pragma unroll
                for (int q = 0; q < NB / 4; q++) {
                    float4 c0 = R0[q], c1 = R1[q], c2 = R2[q], c3 = R3[q];
                    a0 += Lreg[4*q]*c0.x + Lreg[4*q+1]*c0.y + Lreg[4*q+2]*c0.z + Lreg[4*q+3]*c0.w;
                    a1 += Lreg[4*q]*c1.x + Lreg[4*q+1]*c1.y + Lreg[4*q+2]*c1.z + Lreg[4*q+3]*c1.w;
                    a2 += Lreg[4*q]*c2.x + Lreg[4*q+1]*c2.y + Lreg[4*q+2]*c2.z + Lreg[4*q+3]*c2.w;
                    a3 += Lreg[4*q]*c3.x + Lreg[4*q+1]*c3.y + Lreg[4*q+2]*c3.z + Lreg[4*q+3]*c3.w;
                }
                float4 av = *(float4*)&Arow[j];      // 16B-aligned RMW
                av.x -= a0; av.y -= a1; av.z -= a2; av.w -= a3;
                *(float4*)&Arow[j] = av;
                joff += 4 * len;
            }
            for (; j <= tid; j++) {                  // scalar tail (<=3)
                const float4* Lj = (const float4*)(A + joff + kb);
                float a0 = 0.f, a1 = 0.f, a2 = 0.f, a3 = 0.f;
                #pragma unroll
                for (int q = 0; q < NB / 4; q++) {
                    float4 c = Lj[q];
                    a0 += Lreg[4*q]*c.x;  a1 += Lreg[4*q+1]*c.y;
                    a2 += Lreg[4*q+2]*c.z; a3 += Lreg[4*q+3]*c.w;
                }
                Arow[j] -= (a0 + a1) + (a2 + a3);
                joff += (j & ~3) + 4;
            }
        }
        // no CTA barrier: next panel warp only touches rows it itself updated
    }

    // ---- backward solve L^T x = y (2 RHS), blocked ----
    for (int b = NBLK - 1; b >= 0; b--) {
        const int kb = b * NB;
        if (wid == b) {
            float lcol[NB];
            int coff = rowp(kb);
            #pragma unroll
            for (int m = 0; m < NB; m++) {
                lcol[m] = A[coff + tid];             // consecutive lanes: no conflict
                coff += kb + (m & ~3) + 4;
            }
            const float rv = rinvS[tid];
            #pragma unroll
            for (int m = NB - 1; m >= 0; m--) {
                float x1 = __shfl_sync(FULL, v1 * rv, m);
                float x2 = __shfl_sync(FULL, v2 * rv, m);
                if (lane < m) { v1 -= lcol[m] * x1; v2 -= lcol[m] * x2; }
            }
            v1 *= rv; v2 *= rv;
            xs1[tid] = v1; xs2[tid] = v2;
        }
        __syncthreads();
        if (tid < kb) {
            int coff = rowp(kb);
            #pragma unroll
            for (int m = 0; m < NB; m++) {
                float l = A[coff + tid];
                v1 -= l * xs1[kb + m];
                v2 -= l * xs2[kb + m];
                coff += kb + (m & ~3) + 4;
            }
        }
    }

    // v1 = A^{-1}(-chi), v2 = A^{-1} 1
    float s1 = v1, s2 = v2;
    #pragma unroll
    for (int o = 16; o > 0; o >>= 1) {
        s1 += __shfl_xor_sync(FULL, s1, o);
        s2 += __shfl_xor_sync(FULL, s2, o);
    }
    if (lane == 0) { r1s[wid] = s1; r2s[wid] = s2; }
    __syncthreads();
    s1 = r1s[0] + r1s[1] + r1s[2] + r1s[3];
    s2 = r2s[0] + r2s[1] + r2s[2] + r2s[3];

    const float lam = (s1 - Qtot[mol]) / (s2 - 1.0f);
    out[gid] = v1 - lam * v2;
}

extern "C" void kernel_launch(void* const* d_in, const int* in_sizes, int n_in,
                              void* d_out, int out_size)
{
    const float* eneg  = (const float*)d_in[0];
    const float* pos   = (const float*)d_in[1];
    const float* attrs = (const float*)d_in[2];
    const float* hard  = (const float*)d_in[3];
    const float* Qtot  = (const float*)d_in[4];
    const int*   Zs    = (const int*)d_in[6];
    float* out = (float*)d_out;

    const int smem = (TRI_WORDS + 3 * NA + NA * 4) * (int)sizeof(float);  // 37376 B
    cudaFuncSetAttribute(ceq_kernel, cudaFuncAttributeMaxDynamicSharedMemorySize, smem);

    ceq_kernel<<<NMOL, NA, smem>>>(eneg, pos, attrs, hard, Qtot, Zs, out);
}

// round 6
// speedup vs baseline: 3.0014x; 1.0166x over previous
#include <cuda_runtime.h>
#include <math.h>

// ChargeEquilibrationBlock: B=1024 molecules x n=128 atoms.
// Packed-triangle blocked Cholesky (NB=32), fused forward solve,
// WARP-PAIRED load balancing for build + trailing (idle warps help the
// longest rows, lockstep j so L_j reads stay broadcast), and f32x2 packed
// FMA (PTX fma.rn.f32x2) for the trailing dot products. 6 CTAs/SM.

#define NMOL 1024
#define NA   128
#define NB   32
#define NBLK (NA/NB)
#define NE   10
#define FULL 0xffffffffu
#define TRI_WORDS 8448   // rowp(128)

// packed row offset: rows padded to multiple of 4 words (16B aligned)
__device__ __forceinline__ int rowp(int i) {
    const int q = i >> 2, r = i & 3;
    return ((q * (q - 1)) << 3) + ((r * q) << 2) + (i << 2);
}

__device__ __forceinline__ unsigned long long fma2(unsigned long long a,
                                                   unsigned long long b,
                                                   unsigned long long c) {
    unsigned long long d;
    asm("fma.rn.f32x2 %0, %1, %2, %3;" : "=l"(d) : "l"(a), "l"(b), "l"(c));
    return d;
}
__device__ __forceinline__ float hsum2(unsigned long long a) {
    return __uint_as_float((unsigned)a) + __uint_as_float((unsigned)(a >> 32));
}

// build entries (i, j) for j in [jlo, jhi), predicated j < i
__device__ __forceinline__ void build_range(float* A, const float4* pq,
                                            int i, int jlo, int jhi) {
    const float4 pi = pq[i];
    float* Ri = A + rowp(i);
    const float is2 = 0.70710678118654752f;
    for (int j = jlo; j < jhi; j++) {
        if (j < i) {
            float4 p = pq[j];                       // broadcast (lockstep j)
            float dx = pi.x - p.x, dy = pi.y - p.y, dz = pi.z - p.z;
            float d  = sqrtf(dx * dx + dy * dy + dz * dz);
            float gi = rsqrtf(pi.w + p.w);
            Ri[j] = erff(d * is2 * gi) / d;
        }
    }
}

__global__ __launch_bounds__(NA, 6)
void ceq_kernel(const float* __restrict__ eneg,
                const float* __restrict__ pos,
                const float* __restrict__ attrs,
                const float* __restrict__ hard,
                const float* __restrict__ Qtot,
                const int*   __restrict__ Zs,
                float* __restrict__ out)
{
    extern __shared__ float s[];
    float*  A     = s;                    // packed lower triangle
    float*  rinvS = A + TRI_WORDS;        // 128: 1/L_ii
    float*  xs1   = rinvS + NA;           // solve broadcast, RHS 1
    float*  xs2   = xs1 + NA;             // solve broadcast, RHS 2
    float4* pq    = (float4*)(xs2 + NA);  // 128: (x, y, z, sigma)
    __shared__ float r1s[4], r2s[4];

    const int mol  = blockIdx.x;
    const int tid  = threadIdx.x;
    const int lane = tid & 31;
    const int wid  = tid >> 5;
    const int gid  = mol * NA + tid;
    float* Arow = A + rowp(tid);          // row tid: cols 0..tid

    // ---- per-atom setup ----
    const float x = pos[gid * 3 + 0];
    const float y = pos[gid * 3 + 1];
    const float z = pos[gid * 3 + 2];
    const int Z = Zs[gid];
    const float r  = 0.3f + 0.02f * (float)Z;       // COV_RADII[Z]
    const float sg = r * r;
    pq[tid] = make_float4(x, y, z, sg);

    const float* arow = attrs + gid * NE;           // first-max argmax
    int am = 0; float mv = arow[0];
    #pragma unroll
    for (int e = 1; e < NE; e++) { float v = arow[e]; if (v > mv) { mv = v; am = e; } }

    const float diag = hard[am] + 1.0f / (1.7724538509055159f * r);  // sqrt(pi)
    float v1 = -eneg[gid];                          // RHS 1: -chi
    float v2 = 1.0f;                                // RHS 2: ones
    __syncthreads();

    // ---- balanced build: 79 lockstep iterations per warp (was max 127) ----
    if      (wid == 0) { build_range(A, pq, lane,      0, 31);
                         build_range(A, pq, 96 + lane, 0, 48); }
    else if (wid == 1) { build_range(A, pq, 32 + lane, 0, 63);
                         build_range(A, pq, 64 + lane, 0, 16); }
    else if (wid == 2) { build_range(A, pq, 64 + lane, 16, 95); }
    else               { build_range(A, pq, 96 + lane, 48, 127); }
    Arow[tid] = diag;
    __syncthreads();

    // ---- blocked Cholesky with fused forward solve ----
    for (int b = 0; b < NBLK; b++) {
        const int kb = b * NB;

        // (1) panel factorization (warp b) + diag forward solve
        if (wid == b) {
            int doff = rowp(kb);
            for (int m = 0; m < NB; m++) {
                __syncwarp();
                const int cm = kb + m;
                const float dg = A[doff + cm];
                const float rv = rsqrtf(dg);
                float lv = 0.0f;
                if (lane == m) { Arow[cm] = dg * rv; rinvS[cm] = rv; }
                else if (lane > m) { lv = Arow[cm] * rv; Arow[cm] = lv; }
                for (int j = m + 1; j < NB; j++) {
                    float ljm = __shfl_sync(FULL, lv, j);
                    if (j <= lane) Arow[kb + j] -= lv * ljm;
                }
                doff += (cm & ~3) + 4;
            }
            __syncwarp();
            float lrow[NB];
            #pragma unroll
            for (int q = 0; q < NB; q += 4) {
                float4 t4 = *(const float4*)&Arow[kb + q];
                lrow[q] = t4.x; lrow[q+1] = t4.y; lrow[q+2] = t4.z; lrow[q+3] = t4.w;
            }
            const float rv = rinvS[tid];
            #pragma unroll
            for (int m = 0; m < NB; m++) {
                float x1 = __shfl_sync(FULL, v1 * rv, m);
                float x2 = __shfl_sync(FULL, v2 * rv, m);
                if (lane > m) { v1 -= lrow[m] * x1; v2 -= lrow[m] * x2; }
            }
            v1 *= rv; v2 *= rv;
            xs1[tid] = v1; xs2[tid] = v2;
        }
        __syncthreads();                            // panel + rinvS + y visible

        // (2) TRSM below panel (Lreg in registers) + fused RHS update
        if (tid >= kb + NB) {
            float Lreg[NB];
            int poff = rowp(kb);
            #pragma unroll
            for (int m = 0; m < NB; m++) {
                const float* Pm = A + poff + kb;    // panel row m (broadcast)
                float ve = 0.0f, vo = 0.0f;
                #pragma unroll
                for (int t = 0; t < m; t++) {
                    if (t & 1) vo += Lreg[t] * Pm[t];
                    else       ve += Lreg[t] * Pm[t];
                }
                Lreg[m] = (Arow[kb + m] - ve - vo) * rinvS[kb + m];
                poff += kb + (m & ~3) + 4;
            }
            #pragma unroll
            for (int m = 0; m < NB; m += 4)
                *(float4*)&Arow[kb + m] =
                    make_float4(Lreg[m], Lreg[m+1], Lreg[m+2], Lreg[m+3]);
            #pragma unroll
            for (int q = 0; q < NB; q += 4) {       // fused fwd RHS update
                float4 a1 = *(const float4*)&xs1[kb + q];
                float4 a2 = *(const float4*)&xs2[kb + q];
                v1 -= Lreg[q]*a1.x + Lreg[q+1]*a1.y + Lreg[q+2]*a1.z + Lreg[q+3]*a1.w;
                v2 -= Lreg[q]*a2.x + Lreg[q+1]*a2.y + Lreg[q+2]*a2.z + Lreg[q+3]*a2.w;
            }
        }
        __syncthreads();                            // L columns visible

        // (3) trailing update, warp-paired balanced, f32x2 packed FMA
        if (b < 3) {
            int ti, g0, g1;
            if (b == 0) {           // s0=32: rows 32..127; warp0 helps warp3
                ti = (wid == 0) ? 96 + lane : tid;
                g0 = (wid == 3) ? 12 : 0;
                g1 = (wid == 0) ? 12 : (wid == 1 ? 8 : (wid == 2 ? 16 : 24));
            } else if (b == 1) {    // s0=64: warp0->warp2 rows, warp1->warp3 rows
                ti = (wid == 0) ? 64 + lane : (wid == 1 ? 96 + lane : tid);
                g0 = (wid == 2) ? 4 : (wid == 3 ? 8 : 0);
                g1 = (wid == 0) ? 4 : (wid == 1 ? 8 : (wid == 2 ? 8 : 16));
            } else {                // s0=96: rows 96..127, 4-way split
                ti = 96 + lane; g0 = wid * 2; g1 = g0 + 2;
            }
            float* Ti = A + rowp(ti);
            unsigned long long la[16];              // L_ti[kb..kb+31], packed pairs
            const ulonglong2* Lp = (const ulonglong2*)(Ti + kb);
            #pragma unroll
            for (int q = 0; q < 8; q++) {
                ulonglong2 t = Lp[q]; la[2*q] = t.x; la[2*q+1] = t.y;
            }
            const int s0 = kb + NB;
            int j    = s0 + 4 * g0;
            int joff = rowp(j);
            for (int jg = g0; jg < g1; jg++, j += 4) {
                const int len = j + 4;              // padded len of rows j..j+3
                const ulonglong2* R0 = (const ulonglong2*)(A + joff           + kb);
                const ulonglong2* R1 = (const ulonglong2*)(A + joff +   len   + kb);
                const ulonglong2* R2 = (const ulonglong2*)(A + joff + 2*len   + kb);
                const ulonglong2* R3 = (const ulonglong2*)(A + joff + 3*len   + kb);
                unsigned long long a0 = 0ull, a1 = 0ull, a2 = 0ull, a3 = 0ull;
                #pragma unroll
                for (int q = 0; q < 8; q++) {       // broadcast LDS.128 (lockstep j)
                    ulonglong2 c0 = R0[q], c1 = R1[q], c2 = R2[q], c3 = R3[q];
                    a0 = fma2(la[2*q], c0.x, a0); a0 = fma2(la[2*q+1], c0.y, a0);
                    a1 = fma2(la[2*q], c1.x, a1); a1 = fma2(la[2*q+1], c1.y, a1);
                    a2 = fma2(la[2*q], c2.x, a2); a2 = fma2(la[2*q+1], c2.y, a2);
                    a3 = fma2(la[2*q], c3.x, a3); a3 = fma2(la[2*q+1], c3.y, a3);
                }
                if (j <= ti) {                      // partial group spills into padding
                    float4 av = *(float4*)&Ti[j];
                    av.x -= hsum2(a0); av.y -= hsum2(a1);
                    av.z -= hsum2(a2); av.w -= hsum2(a3);
                    *(float4*)&Ti[j] = av;
                }
                joff += 4 * len;
            }
        }
        __syncthreads();                            // cross-warp trailing visible
    }

    // ---- backward solve L^T x = y (2 RHS), blocked ----
    for (int b = NBLK - 1; b >= 0; b--) {
        const int kb = b * NB;
        if (wid == b) {
            float lcol[NB];
            int coff = rowp(kb);
            #pragma unroll
            for (int m = 0; m < NB; m++) {
                lcol[m] = A[coff + tid];            // consecutive lanes: no conflict
                coff += kb + (m & ~3) + 4;
            }
            const float rv = rinvS[tid];
            #pragma unroll
            for (int m = NB - 1; m >= 0; m--) {
                float x1 = __shfl_sync(FULL, v1 * rv, m);
                float x2 = __shfl_sync(FULL, v2 * rv, m);
                if (lane < m) { v1 -= lcol[m] * x1; v2 -= lcol[m] * x2; }
            }
            v1 *= rv; v2 *= rv;
            xs1[tid] = v1; xs2[tid] = v2;
        }
        __syncthreads();
        if (tid < kb) {
            int coff = rowp(kb);
            #pragma unroll
            for (int m = 0; m < NB; m++) {
                float l = A[coff + tid];
                v1 -= l * xs1[kb + m];
                v2 -= l * xs2[kb + m];
                coff += kb + (m & ~3) + 4;
            }
        }
    }

    // v1 = A^{-1}(-chi), v2 = A^{-1} 1
    float s1 = v1, s2 = v2;
    #pragma unroll
    for (int o = 16; o > 0; o >>= 1) {
        s1 += __shfl_xor_sync(FULL, s1, o);
        s2 += __shfl_xor_sync(FULL, s2, o);
    }
    if (lane == 0) { r1s[wid] = s1; r2s[wid] = s2; }
    __syncthreads();
    s1 = r1s[0] + r1s[1] + r1s[2] + r1s[3];
    s2 = r2s[0] + r2s[1] + r2s[2] + r2s[3];

    const float lam = (s1 - Qtot[mol]) / (s2 - 1.0f);
    out[gid] = v1 - lam * v2;
}

extern "C" void kernel_launch(void* const* d_in, const int* in_sizes, int n_in,
                              void* d_out, int out_size)
{
    const float* eneg  = (const float*)d_in[0];
    const float* pos   = (const float*)d_in[1];
    const float* attrs = (const float*)d_in[2];
    const float* hard  = (const float*)d_in[3];
    const float* Qtot  = (const float*)d_in[4];
    const int*   Zs    = (const int*)d_in[6];
    float* out = (float*)d_out;

    const int smem = (TRI_WORDS + 3 * NA + NA * 4) * (int)sizeof(float);  // 37376 B
    cudaFuncSetAttribute(ceq_kernel, cudaFuncAttributeMaxDynamicSharedMemorySize, smem);

    ceq_kernel<<<NMOL, NA, smem>>>(eneg, pos, attrs, hard, Qtot, Zs, out);
}

// round 7
// speedup vs baseline: 3.3709x; 1.1231x over previous
#include <cuda_runtime.h>
#include <math.h>

// ChargeEquilibrationBlock: B=1024 molecules x n=128 atoms.
// Packed-triangle blocked Cholesky (NB=32) with LOOKAHEAD:
//  - panel b+1 is factored by warp b+1 CONCURRENTLY with the other warps'
//    lazy trailing of block b (urgent/next-panel columns updated first),
//  - panel 0 overlaps the matrix build,
//  - TRSM uses float4 panel-row loads,
//  - forward solve fused into factorization; backward solve blocked.
// 6 CTAs/SM. Bordered charge-conservation via 2 RHS + Schur correction.

#define NMOL 1024
#define NA   128
#define NB   32
#define NE   10
#define FULL 0xffffffffu
#define TRI_WORDS 8448   // rowp(128)

typedef unsigned long long ull;

// packed row offset: rows padded to multiple of 4 words (16B aligned)
__device__ __forceinline__ int rowp(int i) {
    const int q = i >> 2, r = i & 3;
    return ((q * (q - 1)) << 3) + ((r * q) << 2) + (i << 2);
}

__device__ __forceinline__ ull fma2(ull a, ull b, ull c) {
    ull d;
    asm("fma.rn.f32x2 %0, %1, %2, %3;" : "=l"(d) : "l"(a), "l"(b), "l"(c));
    return d;
}
__device__ __forceinline__ float hsum2(ull a) {
    return __uint_as_float((unsigned)a) + __uint_as_float((unsigned)(a >> 32));
}

// build entries (i, j) for j in [jlo, jhi), predicated j < i
__device__ __forceinline__ void build_range(float* A, const float4* pq,
                                            int i, int jlo, int jhi) {
    const float4 pi = pq[i];
    float* Ri = A + rowp(i);
    const float is2 = 0.70710678118654752f;
    for (int j = jlo; j < jhi; j++) {
        if (j < i) {
            float4 p = pq[j];                       // broadcast (lockstep j)
            float dx = pi.x - p.x, dy = pi.y - p.y, dz = pi.z - p.z;
            float sq = dx * dx + dy * dy + dz * dz;
            float ri = rsqrtf(sq);                  // 1/d
            float gi = rsqrtf(pi.w + p.w);          // 1/gamma
            Ri[j] = erff(sq * ri * is2 * gi) * ri;  // erf(d/(sqrt2*gamma))/d
        }
    }
}

// trailing units: row ti, j-groups [g0, g1) of block at column base s.
// reloads own L row from smem; lockstep j across the warp (broadcast loads).
__device__ __forceinline__ void trail_units(float* A, int ti, int s,
                                            int g0, int g1) {
    float* Ti = A + rowp(ti);
    ull la[16];
    const ulonglong2* Lp = (const ulonglong2*)(Ti + s);
    #pragma unroll
    for (int q = 0; q < 8; q++) { ulonglong2 t = Lp[q]; la[2*q] = t.x; la[2*q+1] = t.y; }
    int j    = s + NB + 4 * g0;
    int joff = rowp(j);
    for (int jg = g0; jg < g1; jg++, j += 4) {
        const int len = j + 4;                      // padded row length (j mult 4)
        const ulonglong2* R0 = (const ulonglong2*)(A + joff           + s);
        const ulonglong2* R1 = (const ulonglong2*)(A + joff +   len   + s);
        const ulonglong2* R2 = (const ulonglong2*)(A + joff + 2*len   + s);
        const ulonglong2* R3 = (const ulonglong2*)(A + joff + 3*len   + s);
        ull a0 = 0ull, a1 = 0ull, a2 = 0ull, a3 = 0ull;
        #pragma unroll
        for (int q = 0; q < 8; q++) {               // broadcast LDS.128, lockstep j
            ulonglong2 c0 = R0[q], c1 = R1[q], c2 = R2[q], c3 = R3[q];
            a0 = fma2(la[2*q], c0.x, a0); a0 = fma2(la[2*q+1], c0.y, a0);
            a1 = fma2(la[2*q], c1.x, a1); a1 = fma2(la[2*q+1], c1.y, a1);
            a2 = fma2(la[2*q], c2.x, a2); a2 = fma2(la[2*q+1], c2.y, a2);
            a3 = fma2(la[2*q], c3.x, a3); a3 = fma2(la[2*q+1], c3.y, a3);
        }
        if (j <= ti) {                              // partial group -> padding
            float4 av = *(float4*)&Ti[j];
            av.x -= hsum2(a0); av.y -= hsum2(a1);
            av.z -= hsum2(a2); av.w -= hsum2(a3);
            *(float4*)&Ti[j] = av;
        }
        joff += 4 * len;
    }
}

// panel factorization (warp-internal, rows/cols kb..kb+31) + fused diag
// forward solve publishing y into xs1/xs2. Caller: the single owner warp.
__device__ __forceinline__ void panel_and_y(float* A, float* rinvS,
                                            float* xs1, float* xs2,
                                            float* Arow, int kb, int lane,
                                            int tid, float& v1, float& v2) {
    int doff = rowp(kb);
    for (int m = 0; m < NB; m++) {
        __syncwarp();
        const int cm = kb + m;
        const float dg = A[doff + cm];              // updated diag (broadcast)
        const float rv = rsqrtf(dg);
        float lv = 0.0f;
        if (lane == m) { Arow[cm] = dg * rv; rinvS[cm] = rv; }
        else if (lane > m) { lv = Arow[cm] * rv; Arow[cm] = lv; }
        for (int j = m + 1; j < NB; j++) {          // uniform trip: shfl legal
            float ljm = __shfl_sync(FULL, lv, j);
            if (j <= lane) Arow[kb + j] -= lv * ljm;
        }
        doff += (cm & ~3) + 4;
    }
    __syncwarp();
    float lrow[NB];
    #pragma unroll
    for (int q = 0; q < NB; q += 4) {
        float4 t4 = *(const float4*)&Arow[kb + q];
        lrow[q] = t4.x; lrow[q+1] = t4.y; lrow[q+2] = t4.z; lrow[q+3] = t4.w;
    }
    const float rv = rinvS[tid];
    #pragma unroll
    for (int m = 0; m < NB; m++) {
        float x1 = __shfl_sync(FULL, v1 * rv, m);
        float x2 = __shfl_sync(FULL, v2 * rv, m);
        if (lane > m) { v1 -= lrow[m] * x1; v2 -= lrow[m] * x2; }
    }
    v1 *= rv; v2 *= rv;                             // y for this row
    xs1[tid] = v1; xs2[tid] = v2;
}

__global__ __launch_bounds__(NA, 6)
void ceq_kernel(const float* __restrict__ eneg,
                const float* __restrict__ pos,
                const float* __restrict__ attrs,
                const float* __restrict__ hard,
                const float* __restrict__ Qtot,
                const int*   __restrict__ Zs,
                float* __restrict__ out)
{
    extern __shared__ float s[];
    float*  A     = s;                    // packed lower triangle
    float*  rinvS = A + TRI_WORDS;        // 128: 1/L_ii
    float*  xs1   = rinvS + NA;           // solve broadcast, RHS 1
    float*  xs2   = xs1 + NA;             // solve broadcast, RHS 2
    float4* pq    = (float4*)(xs2 + NA);  // 128: (x, y, z, sigma)
    __shared__ float r1s[4], r2s[4];

    const int mol  = blockIdx.x;
    const int tid  = threadIdx.x;
    const int lane = tid & 31;
    const int wid  = tid >> 5;
    const int gid  = mol * NA + tid;
    float* Arow = A + rowp(tid);

    // ---- per-atom setup ----
    const float x = pos[gid * 3 + 0];
    const float y = pos[gid * 3 + 1];
    const float z = pos[gid * 3 + 2];
    const int Z = Zs[gid];
    const float r  = 0.3f + 0.02f * (float)Z;       // COV_RADII[Z]
    const float sg = r * r;
    pq[tid] = make_float4(x, y, z, sg);

    const float* arow = attrs + gid * NE;           // first-max argmax
    int am = 0; float mv = arow[0];
    #pragma unroll
    for (int e = 1; e < NE; e++) { float v = arow[e]; if (v > mv) { mv = v; am = e; } }

    const float diag = hard[am] + 1.0f / (1.7724538509055159f * r);  // sqrt(pi)
    float v1 = -eneg[gid];                          // RHS 1: -chi
    float v2 = 1.0f;                                // RHS 2: ones
    __syncthreads();                                // pq visible

    Arow[tid] = diag;                               // own diagonal

    // ---- build with panel-0 overlap ----
    if (wid == 0) {
        build_range(A, pq, lane, 0, 31);            // rows 0..31 (panel block)
        __syncwarp();
        panel_and_y(A, rinvS, xs1, xs2, Arow, 0, lane, tid, v1, v2);
    } else if (wid == 1) {
        build_range(A, pq, 32 + lane, 0, 63);
        build_range(A, pq, 96 + lane, 0, 32);
    } else if (wid == 2) {
        build_range(A, pq, 64 + lane, 0, 95);
    } else {
        build_range(A, pq, 96 + lane, 32, 127);
    }
    __syncthreads();                                // BAR_A(0): build + panel0 + y0

    // ---- lookahead factorization: blocks 0..2 carry TRSM + trailing;
    //      panel b+1 runs concurrently with lazy trailing of block b ----
    for (int b = 0; b < 3; b++) {
        const int sb = 32 * b;

        // TRSM_b: rows below panel -> Lreg, float4 panel loads, fused fwd RHS
        if (tid >= sb + NB) {
            float Lreg[NB];
            int poff = rowp(sb);
            #pragma unroll
            for (int m = 0; m < NB; m++) {
                const float* Pm = A + poff + sb;    // panel row m (broadcast)
                float ve = 0.0f, vo = 0.0f;
                #pragma unroll
                for (int q = 0; q < NB / 4; q++) {
                    if (4 * q + 4 <= m) {           // full quads (compile-time)
                        float4 c = *(const float4*)(Pm + 4 * q);
                        ve += Lreg[4*q    ] * c.x + Lreg[4*q + 2] * c.z;
                        vo += Lreg[4*q + 1] * c.y + Lreg[4*q + 3] * c.w;
                    }
                }
                #pragma unroll
                for (int t = m & ~3; t < m; t++)    // remainder scalars
                    ve += Lreg[t] * Pm[t];
                Lreg[m] = (Arow[sb + m] - ve - vo) * rinvS[sb + m];
                poff += sb + (m & ~3) + 4;
            }
            #pragma unroll
            for (int m = 0; m < NB; m += 4)
                *(float4*)&Arow[sb + m] =
                    make_float4(Lreg[m], Lreg[m+1], Lreg[m+2], Lreg[m+3]);
            #pragma unroll
            for (int q = 0; q < NB; q += 4) {       // fused forward RHS update
                float4 a1 = *(const float4*)&xs1[sb + q];
                float4 a2 = *(const float4*)&xs2[sb + q];
                v1 -= Lreg[q]*a1.x + Lreg[q+1]*a1.y + Lreg[q+2]*a1.z + Lreg[q+3]*a1.w;
                v2 -= Lreg[q]*a2.x + Lreg[q+1]*a2.y + Lreg[q+2]*a2.z + Lreg[q+3]*a2.w;
            }
        }
        __syncthreads();                            // BAR_B(b): L columns visible

        // overlap slot: warp b+1 -> urgent own-rows + panel b+1;
        // other warps -> balanced urgent-2 + lazy trailing of block b.
        if (b == 0) {
            if (wid == 1) {
                trail_units(A, tid, 0, 0, 8);       // own rows 32..63, cols 32..63
                __syncwarp();
                panel_and_y(A, rinvS, xs1, xs2, Arow, 32, lane, tid, v1, v2);
            }
            else if (wid == 2) trail_units(A, 64 + lane, 0,  0, 16);
            else if (wid == 3) trail_units(A, 96 + lane, 0,  0, 12);
            else               trail_units(A, 96 + lane, 0, 12, 24);
        } else if (b == 1) {
            if (wid == 2) {
                trail_units(A, tid, 32, 0, 8);      // own rows 64..95, cols 64..95
                __syncwarp();
                panel_and_y(A, rinvS, xs1, xs2, Arow, 64, lane, tid, v1, v2);
            }
            else if (wid == 3) trail_units(A, 96 + lane, 32, 0, 8);
            else if (wid == 1) trail_units(A, 96 + lane, 32, 8, 16);
            // wid 0: no work this slot
        } else {  // b == 2
            if (wid == 3) {
                trail_units(A, tid, 64, 0, 8);      // own rows 96..127, cols 96..127
                __syncwarp();
                panel_and_y(A, rinvS, xs1, xs2, Arow, 96, lane, tid, v1, v2);
            }
        }
        __syncthreads();                            // BAR_A(b+1)
    }
    // factorization + forward solve complete: v = y

    // ---- backward solve L^T x = y (2 RHS), blocked ----
    for (int b = 3; b >= 0; b--) {
        const int kb = b * NB;
        if (wid == b) {
            float lcol[NB];
            int coff = rowp(kb);
            #pragma unroll
            for (int m = 0; m < NB; m++) {
                lcol[m] = A[coff + tid];            // consecutive lanes: no conflict
                coff += kb + (m & ~3) + 4;
            }
            const float rv = rinvS[tid];
            #pragma unroll
            for (int m = NB - 1; m >= 0; m--) {
                float x1 = __shfl_sync(FULL, v1 * rv, m);
                float x2 = __shfl_sync(FULL, v2 * rv, m);
                if (lane < m) { v1 -= lcol[m] * x1; v2 -= lcol[m] * x2; }
            }
            v1 *= rv; v2 *= rv;
            xs1[tid] = v1; xs2[tid] = v2;
        }
        __syncthreads();
        if (tid < kb) {
            int coff = rowp(kb);
            #pragma unroll
            for (int m = 0; m < NB; m++) {
                float l = A[coff + tid];
                v1 -= l * xs1[kb + m];
                v2 -= l * xs2[kb + m];
                coff += kb + (m & ~3) + 4;
            }
        }
    }

    // v1 = A^{-1}(-chi), v2 = A^{-1} 1
    float s1 = v1, s2 = v2;
    #pragma unroll
    for (int o = 16; o > 0; o >>= 1) {
        s1 += __shfl_xor_sync(FULL, s1, o);
        s2 += __shfl_xor_sync(FULL, s2, o);
    }
    if (lane == 0) { r1s[wid] = s1; r2s[wid] = s2; }
    __syncthreads();
    s1 = r1s[0] + r1s[1] + r1s[2] + r1s[3];
    s2 = r2s[0] + r2s[1] + r2s[2] + r2s[3];

    const float lam = (s1 - Qtot[mol]) / (s2 - 1.0f);
    out[gid] = v1 - lam * v2;
}

extern "C" void kernel_launch(void* const* d_in, const int* in_sizes, int n_in,
                              void* d_out, int out_size)
{
    const float* eneg  = (const float*)d_in[0];
    const float* pos   = (const float*)d_in[1];
    const float* attrs = (const float*)d_in[2];
    const float* hard  = (const float*)d_in[3];
    const float* Qtot  = (const float*)d_in[4];
    const int*   Zs    = (const int*)d_in[6];
    float* out = (float*)d_out;

    const int smem = (TRI_WORDS + 3 * NA + NA * 4) * (int)sizeof(float);  // 37376 B
    cudaFuncSetAttribute(ceq_kernel, cudaFuncAttributeMaxDynamicSharedMemorySize, smem);

    ceq_kernel<<<NMOL, NA, smem>>>(eneg, pos, attrs, hard, Qtot, Zs, out);
}